// round 11
// baseline (speedup 1.0000x reference)
#include <cuda_runtime.h>

// Problem constants (fixed by the reference)
#define NN   10000
#define FIN  50
#define HID  512
#define FOUT 121
#define NE   160000

// ---------------- scratch (static device globals: no allocation) ----------------
__device__ int   g_edges[2 * NE];      // [0,NE): src, [NE,2NE): dst (int32, converted)
__device__ int   g_is64;               // dtype flag for the raw edge buffer
__device__ float g_deg [NN];
__device__ float g_inv [NN];
__device__ float g_agg1[NN * FIN];     // mean-aggregated x
__device__ float g_h   [NN * HID];     // layer-1 output
__device__ float g_p   [NN * FOUT];    // h @ W2_l (pre-aggregation)
__device__ float g_aggp[NN * FOUT];    // segment-sum of g_p

// ---------------- edge dtype detection + conversion ----------------
// If the buffer holds int64 (values < 2^31, non-negative), every odd 32-bit
// word is zero. If int32, odd words are random node ids in [0, NN).
__global__ void k_detect(const int* __restrict__ ei_raw) {
    __shared__ int nz;
    if (threadIdx.x == 0) nz = 0;
    __syncthreads();
    int local = 0;
    for (int i = threadIdx.x; i < 1024; i += blockDim.x)
        if (ei_raw[2 * i + 1] != 0) local = 1;
    if (local) atomicOr(&nz, 1);
    __syncthreads();
    if (threadIdx.x == 0) g_is64 = (nz == 0) ? 1 : 0;
}

__global__ void k_convert(const void* __restrict__ ei_raw) {
    int i = blockIdx.x * blockDim.x + threadIdx.x;
    if (i < 2 * NE) {
        int v;
        if (g_is64) v = (int)((const long long*)ei_raw)[i];
        else        v = ((const int*)ei_raw)[i];
        g_edges[i] = v;
    }
}

// ---------------- small elementwise kernels ----------------
__global__ void k_zero(float* __restrict__ p, int n) {
    int i = blockIdx.x * blockDim.x + threadIdx.x;
    if (i < n) p[i] = 0.0f;
}

__global__ void k_deg() {
    int e = blockIdx.x * blockDim.x + threadIdx.x;
    if (e < NE) {
        int d = g_edges[NE + e];
        if (d >= 0 && d < NN) atomicAdd(&g_deg[d], 1.0f);
    }
}

__global__ void k_inv() {
    int i = blockIdx.x * blockDim.x + threadIdx.x;
    if (i < NN) g_inv[i] = 1.0f / fmaxf(g_deg[i], 1.0f);
}

// scatter x[src] rows into g_agg1[dst]; 64 threads per edge, f < FIN active.
// Consecutive f -> consecutive addresses: coalesced LDG + coalesced scalar RED.
__global__ void k_scatter1(const float* __restrict__ x) {
    long long idx = (long long)blockIdx.x * blockDim.x + threadIdx.x;
    int e = (int)(idx >> 6);
    int f = (int)(idx & 63);
    if (e < NE && f < FIN) {
        int s = g_edges[e];
        int d = g_edges[NE + e];
        if ((unsigned)s < NN && (unsigned)d < NN)
            atomicAdd(&g_agg1[d * FIN + f], x[s * FIN + f]);
    }
}

__global__ void k_scale1() {
    int i = blockIdx.x * blockDim.x + threadIdx.x;
    if (i < NN * FIN) g_agg1[i] *= g_inv[i / FIN];
}

// scatter p[src] rows into g_aggp[dst]; 128 threads per edge, f < FOUT active.
__global__ void k_scatter2() {
    long long idx = (long long)blockIdx.x * blockDim.x + threadIdx.x;
    int e = (int)(idx >> 7);
    int f = (int)(idx & 127);
    if (e < NE && f < FOUT) {
        int s = g_edges[e];
        int d = g_edges[NE + e];
        if ((unsigned)s < NN && (unsigned)d < NN)
            atomicAdd(&g_aggp[d * FOUT + f], g_p[s * FOUT + f]);
    }
}

// out += mean_agg(p)
__global__ void k_final(float* __restrict__ out) {
    int i = blockIdx.x * blockDim.x + threadIdx.x;
    if (i < NN * FOUT) out[i] += g_aggp[i] * g_inv[i / FOUT];
}

// ---------------- fp32 tiled GEMM, dual-A (C = A1@W1 + A2@W2 + b, relu) ----------------
// Layer 1: h = relu(agg1@W1_l + x@W1_r + b1), M=NN, N=HID, K=FIN.
__global__ __launch_bounds__(256)
void gemm1_k(const float* __restrict__ A1, const float* __restrict__ W1,
             const float* __restrict__ A2, const float* __restrict__ W2,
             const float* __restrict__ bias, float* __restrict__ C,
             int M, int N, int K)
{
    constexpr int BM = 64, BN = 64, BK = 16, TM = 4, TN = 4;
    __shared__ float sA1[BK][BM];
    __shared__ float sW1[BK][BN];
    __shared__ float sA2[BK][BM];
    __shared__ float sW2[BK][BN];

    const int tid = threadIdx.x;
    const int tx = tid % 16;          // N direction
    const int ty = tid / 16;          // M direction
    const int m0 = blockIdx.y * BM;
    const int n0 = blockIdx.x * BN;

    float acc[TM][TN];
#pragma unroll
    for (int i = 0; i < TM; i++)
#pragma unroll
        for (int j = 0; j < TN; j++) acc[i][j] = 0.0f;

    const int arow = tid / 4;            // 0..63
    const int ac0  = (tid % 4) * 4;      // 0,4,8,12
    const int wcol = tid % 64;           // 0..63
    const int wr0  = tid / 64;           // 0..3

    for (int k0 = 0; k0 < K; k0 += BK) {
#pragma unroll
        for (int i = 0; i < 4; i++) {
            int k = k0 + ac0 + i;
            int m = m0 + arow;
            float v1 = 0.0f, v2 = 0.0f;
            if (m < M && k < K) {
                v1 = A1[(long)m * K + k];
                v2 = A2[(long)m * K + k];
            }
            sA1[ac0 + i][arow] = v1;
            sA2[ac0 + i][arow] = v2;
        }
#pragma unroll
        for (int it = 0; it < 4; it++) {
            int kr = wr0 + it * 4;
            int k = k0 + kr;
            int n = n0 + wcol;
            float v1 = 0.0f, v2 = 0.0f;
            if (k < K && n < N) {
                v1 = W1[(long)k * N + n];
                v2 = W2[(long)k * N + n];
            }
            sW1[kr][wcol] = v1;
            sW2[kr][wcol] = v2;
        }
        __syncthreads();

#pragma unroll
        for (int kk = 0; kk < BK; kk++) {
            float a1[TM], w1[TN], a2[TM], w2[TN];
#pragma unroll
            for (int i = 0; i < TM; i++) {
                a1[i] = sA1[kk][ty * TM + i];
                a2[i] = sA2[kk][ty * TM + i];
            }
#pragma unroll
            for (int j = 0; j < TN; j++) {
                w1[j] = sW1[kk][tx * TN + j];
                w2[j] = sW2[kk][tx * TN + j];
            }
#pragma unroll
            for (int i = 0; i < TM; i++)
#pragma unroll
                for (int j = 0; j < TN; j++) {
                    acc[i][j] += a1[i] * w1[j];
                    acc[i][j] += a2[i] * w2[j];
                }
        }
        __syncthreads();
    }

#pragma unroll
    for (int i = 0; i < TM; i++) {
        int m = m0 + ty * TM + i;
        if (m >= M) continue;
#pragma unroll
        for (int j = 0; j < TN; j++) {
            int n = n0 + tx * TN + j;
            if (n >= N) continue;
            float v = acc[i][j] + bias[n];
            C[(long)m * N + n] = fmaxf(v, 0.0f);
        }
    }
}

// ---------------- fp32 tiled GEMM, dual-B: one A pass, two outputs ----------------
// Layer 2: C1 = A@Wa (no bias), C2 = A@Wb + bias. M=NN, N=FOUT, K=HID.
// Shares the A smem tile between both products: halves traffic on the big
// operand h [10000 x 512].
__global__ __launch_bounds__(256)
void gemm2_k(const float* __restrict__ A,
             const float* __restrict__ Wa, const float* __restrict__ Wb,
             const float* __restrict__ bias,
             float* __restrict__ C1, float* __restrict__ C2,
             int M, int N, int K)
{
    constexpr int BM = 64, BN = 64, BK = 16, TM = 4, TN = 4;
    __shared__ float sA [BK][BM];
    __shared__ float sWa[BK][BN];
    __shared__ float sWb[BK][BN];

    const int tid = threadIdx.x;
    const int tx = tid % 16;
    const int ty = tid / 16;
    const int m0 = blockIdx.y * BM;
    const int n0 = blockIdx.x * BN;

    float acc1[TM][TN], acc2[TM][TN];
#pragma unroll
    for (int i = 0; i < TM; i++)
#pragma unroll
        for (int j = 0; j < TN; j++) { acc1[i][j] = 0.0f; acc2[i][j] = 0.0f; }

    const int arow = tid / 4;
    const int ac0  = (tid % 4) * 4;
    const int wcol = tid % 64;
    const int wr0  = tid / 64;

    for (int k0 = 0; k0 < K; k0 += BK) {
#pragma unroll
        for (int i = 0; i < 4; i++) {
            int k = k0 + ac0 + i;
            int m = m0 + arow;
            float v = 0.0f;
            if (m < M && k < K) v = A[(long)m * K + k];
            sA[ac0 + i][arow] = v;
        }
#pragma unroll
        for (int it = 0; it < 4; it++) {
            int kr = wr0 + it * 4;
            int k = k0 + kr;
            int n = n0 + wcol;
            float va = 0.0f, vb = 0.0f;
            if (k < K && n < N) {
                va = Wa[(long)k * N + n];
                vb = Wb[(long)k * N + n];
            }
            sWa[kr][wcol] = va;
            sWb[kr][wcol] = vb;
        }
        __syncthreads();

#pragma unroll
        for (int kk = 0; kk < BK; kk++) {
            float a[TM], wa[TN], wb[TN];
#pragma unroll
            for (int i = 0; i < TM; i++) a[i] = sA[kk][ty * TM + i];
#pragma unroll
            for (int j = 0; j < TN; j++) {
                wa[j] = sWa[kk][tx * TN + j];
                wb[j] = sWb[kk][tx * TN + j];
            }
#pragma unroll
            for (int i = 0; i < TM; i++)
#pragma unroll
                for (int j = 0; j < TN; j++) {
                    acc1[i][j] += a[i] * wa[j];
                    acc2[i][j] += a[i] * wb[j];
                }
        }
        __syncthreads();
    }

#pragma unroll
    for (int i = 0; i < TM; i++) {
        int m = m0 + ty * TM + i;
        if (m >= M) continue;
#pragma unroll
        for (int j = 0; j < TN; j++) {
            int n = n0 + tx * TN + j;
            if (n >= N) continue;
            C1[(long)m * N + n] = acc1[i][j];
            C2[(long)m * N + n] = acc2[i][j] + bias[n];
        }
    }
}

// ---------------- launch ----------------
extern "C" void kernel_launch(void* const* d_in, const int* in_sizes, int n_in,
                              void* d_out, int out_size)
{
    const float* x   = (const float*)d_in[0];
    const void*  ei  = d_in[1];
    const float* W1l = (const float*)d_in[2];
    const float* W1r = (const float*)d_in[3];
    const float* b1  = (const float*)d_in[4];
    const float* W2l = (const float*)d_in[5];
    const float* W2r = (const float*)d_in[6];
    const float* b2  = (const float*)d_in[7];
    float*       out = (float*)d_out;

    float *p_deg, *p_agg1, *p_h, *p_p, *p_aggp;
    cudaGetSymbolAddress((void**)&p_deg,  g_deg);
    cudaGetSymbolAddress((void**)&p_agg1, g_agg1);
    cudaGetSymbolAddress((void**)&p_h,    g_h);
    cudaGetSymbolAddress((void**)&p_p,    g_p);
    cudaGetSymbolAddress((void**)&p_aggp, g_aggp);

    // detect edge dtype, convert to int32
    k_detect<<<1, 256>>>((const int*)ei);
    k_convert<<<(2 * NE + 255) / 256, 256>>>(ei);

    // zero atomic targets
    k_zero<<<(NN + 255) / 256, 256>>>(p_deg, NN);
    k_zero<<<(NN * FIN + 255) / 256, 256>>>(p_agg1, NN * FIN);
    k_zero<<<(NN * FOUT + 255) / 256, 256>>>(p_aggp, NN * FOUT);

    // degrees + reciprocal
    k_deg<<<(NE + 255) / 256, 256>>>();
    k_inv<<<(NN + 255) / 256, 256>>>();

    // layer 1: aggregate x (narrow, 50 feats), scale, fused dual-A GEMM + bias + relu
    {
        long long total = (long long)NE * 64;
        k_scatter1<<<(unsigned)((total + 255) / 256), 256>>>(x);
        k_scale1<<<(NN * FIN + 255) / 256, 256>>>();
        dim3 grid((HID + 63) / 64, (NN + 63) / 64);
        gemm1_k<<<grid, 256>>>(p_agg1, W1l, x, W1r, b1, p_h, NN, HID, FIN);
    }

    // layer 2: fused dual-B GEMM (p = h@W2_l, out = h@W2_r + b2),
    // aggregate p (narrow, 121 feats), out += mean_agg(p)
    {
        dim3 grid((FOUT + 63) / 64, (NN + 63) / 64);
        gemm2_k<<<grid, 256>>>(p_h, W2l, W2r, b2, p_p, out, NN, FOUT, HID);
        long long total = (long long)NE * 128;
        k_scatter2<<<(unsigned)((total + 255) / 256), 256>>>();
        k_final<<<(NN * FOUT + 255) / 256, 256>>>(out);
    }
}

// round 12
// speedup vs baseline: 1.2915x; 1.2915x over previous
#include <cuda_runtime.h>

// Problem constants (fixed by the reference)
#define NN   10000
#define FIN  50
#define HID  512
#define FOUT 121
#define NE   160000

// ---------------- scratch (static device globals: no allocation) ----------------
__device__ int   g_edges[2 * NE];      // [0,NE): src, [NE,2NE): dst (int32, converted)
__device__ int   g_is64;               // dtype flag for the raw edge buffer
__device__ int   g_cnt [NN];           // in-degree histogram
__device__ int   g_fill[NN];           // bucket fill cursors
__device__ int   g_off [NN + 1];       // CSR row offsets (by dst)
__device__ int   g_csr [NE];           // src ids grouped by dst
__device__ float g_agg1[NN * FIN];     // mean-aggregated x
__device__ float g_h   [NN * HID];     // layer-1 output
__device__ float g_p   [NN * FOUT];    // h @ W2_l (pre-aggregation)

// ---------------- edge dtype detection + conversion ----------------
// If the buffer holds int64 (values < 2^31, non-negative), every odd 32-bit
// word is zero. If int32, odd words are random node ids in [0, NN).
__global__ void k_detect(const int* __restrict__ ei_raw) {
    __shared__ int nz;
    if (threadIdx.x == 0) nz = 0;
    __syncthreads();
    int local = 0;
    for (int i = threadIdx.x; i < 1024; i += blockDim.x)
        if (ei_raw[2 * i + 1] != 0) local = 1;
    if (local) atomicOr(&nz, 1);
    __syncthreads();
    if (threadIdx.x == 0) g_is64 = (nz == 0) ? 1 : 0;
}

__global__ void k_convert(const void* __restrict__ ei_raw) {
    int i = blockIdx.x * blockDim.x + threadIdx.x;
    if (i < 2 * NE) {
        int v;
        if (g_is64) v = (int)((const long long*)ei_raw)[i];
        else        v = ((const int*)ei_raw)[i];
        g_edges[i] = v;
    }
}

// ---------------- CSR build: histogram -> scan -> fill ----------------
__global__ void k_zero2() {
    int i = blockIdx.x * blockDim.x + threadIdx.x;
    if (i < NN) { g_cnt[i] = 0; g_fill[i] = 0; }
}

__global__ void k_hist() {
    int e = blockIdx.x * blockDim.x + threadIdx.x;
    if (e < NE) {
        int d = g_edges[NE + e];
        if ((unsigned)d < NN) atomicAdd(&g_cnt[d], 1);
    }
}

// Exclusive scan of g_cnt into g_off. Single block, 1024 threads, 10 items each
// (covers 10240 >= NN). Hillis-Steele on per-thread partials.
__global__ void k_scan() {
    __shared__ int tmp[1024];
    const int t = threadIdx.x;
    const int idx0 = t * 10;
    int local[10];
    int part = 0;
#pragma unroll
    for (int j = 0; j < 10; j++) {
        int idx = idx0 + j;
        int c = (idx < NN) ? g_cnt[idx] : 0;
        local[j] = c;
        part += c;
    }
    tmp[t] = part;
    __syncthreads();
    for (int off = 1; off < 1024; off <<= 1) {
        int v = (t >= off) ? tmp[t - off] : 0;
        __syncthreads();
        tmp[t] += v;
        __syncthreads();
    }
    int excl = tmp[t] - part;   // exclusive prefix of this thread's chunk
#pragma unroll
    for (int j = 0; j < 10; j++) {
        int idx = idx0 + j;
        if (idx < NN) g_off[idx] = excl;
        excl += local[j];
    }
    if (t == 1023) g_off[NN] = tmp[1023];
}

__global__ void k_fill() {
    int e = blockIdx.x * blockDim.x + threadIdx.x;
    if (e < NE) {
        int s = g_edges[e];
        int d = g_edges[NE + e];
        if ((unsigned)s < NN && (unsigned)d < NN) {
            int pos = g_off[d] + atomicAdd(&g_fill[d], 1);
            g_csr[pos] = s;
        }
    }
}

// ---------------- gather aggregations (no atomics) ----------------
// Layer 1: g_agg1[d] = mean over incoming src of x[src].  One warp per dst.
// lane covers f and f+32 (FIN=50 <= 64). Coalesced: lanes -> consecutive f.
__global__ void k_agg1(const float* __restrict__ x) {
    int gid  = blockIdx.x * blockDim.x + threadIdx.x;
    int w    = gid >> 5;          // dst row
    int lane = gid & 31;
    if (w >= NN) return;
    int b = g_off[w], e = g_off[w + 1];
    float s0 = 0.0f, s1 = 0.0f;
    for (int i = b; i < e; i++) {
        int src = g_csr[i];
        const float* row = x + (long)src * FIN;
        s0 += row[lane];
        if (lane + 32 < FIN) s1 += row[lane + 32];
    }
    float inv = 1.0f / fmaxf((float)(e - b), 1.0f);
    g_agg1[w * FIN + lane] = s0 * inv;
    if (lane + 32 < FIN) g_agg1[w * FIN + lane + 32] = s1 * inv;
}

// Layer 2: out[d] += mean over incoming src of g_p[src]. One warp per dst.
// lane covers f, f+32, f+64, f+96 (FOUT=121 <= 128). Fuses the old k_final.
__global__ void k_agg2(float* __restrict__ out) {
    int gid  = blockIdx.x * blockDim.x + threadIdx.x;
    int w    = gid >> 5;
    int lane = gid & 31;
    if (w >= NN) return;
    int b = g_off[w], e = g_off[w + 1];
    float s0 = 0.0f, s1 = 0.0f, s2 = 0.0f, s3 = 0.0f;
    for (int i = b; i < e; i++) {
        int src = g_csr[i];
        const float* row = g_p + (long)src * FOUT;
        s0 += row[lane];
        s1 += row[lane + 32];
        s2 += row[lane + 64];
        if (lane + 96 < FOUT) s3 += row[lane + 96];
    }
    float inv = 1.0f / fmaxf((float)(e - b), 1.0f);
    float* orow = out + (long)w * FOUT;
    orow[lane]      += s0 * inv;
    orow[lane + 32] += s1 * inv;
    orow[lane + 64] += s2 * inv;
    if (lane + 96 < FOUT) orow[lane + 96] += s3 * inv;
}

// ---------------- fp32 tiled GEMM, dual-A (C = A1@W1 + A2@W2 + b, relu) ----------------
// Layer 1: h = relu(agg1@W1_l + x@W1_r + b1), M=NN, N=HID, K=FIN.
__global__ __launch_bounds__(256)
void gemm1_k(const float* __restrict__ A1, const float* __restrict__ W1,
             const float* __restrict__ A2, const float* __restrict__ W2,
             const float* __restrict__ bias, float* __restrict__ C,
             int M, int N, int K)
{
    constexpr int BM = 64, BN = 64, BK = 16, TM = 4, TN = 4;
    __shared__ float sA1[BK][BM];
    __shared__ float sW1[BK][BN];
    __shared__ float sA2[BK][BM];
    __shared__ float sW2[BK][BN];

    const int tid = threadIdx.x;
    const int tx = tid % 16;          // N direction
    const int ty = tid / 16;          // M direction
    const int m0 = blockIdx.y * BM;
    const int n0 = blockIdx.x * BN;

    float acc[TM][TN];
#pragma unroll
    for (int i = 0; i < TM; i++)
#pragma unroll
        for (int j = 0; j < TN; j++) acc[i][j] = 0.0f;

    const int arow = tid / 4;            // 0..63
    const int ac0  = (tid % 4) * 4;      // 0,4,8,12
    const int wcol = tid % 64;           // 0..63
    const int wr0  = tid / 64;           // 0..3

    for (int k0 = 0; k0 < K; k0 += BK) {
#pragma unroll
        for (int i = 0; i < 4; i++) {
            int k = k0 + ac0 + i;
            int m = m0 + arow;
            float v1 = 0.0f, v2 = 0.0f;
            if (m < M && k < K) {
                v1 = A1[(long)m * K + k];
                v2 = A2[(long)m * K + k];
            }
            sA1[ac0 + i][arow] = v1;
            sA2[ac0 + i][arow] = v2;
        }
#pragma unroll
        for (int it = 0; it < 4; it++) {
            int kr = wr0 + it * 4;
            int k = k0 + kr;
            int n = n0 + wcol;
            float v1 = 0.0f, v2 = 0.0f;
            if (k < K && n < N) {
                v1 = W1[(long)k * N + n];
                v2 = W2[(long)k * N + n];
            }
            sW1[kr][wcol] = v1;
            sW2[kr][wcol] = v2;
        }
        __syncthreads();

#pragma unroll
        for (int kk = 0; kk < BK; kk++) {
            float a1[TM], w1[TN], a2[TM], w2[TN];
#pragma unroll
            for (int i = 0; i < TM; i++) {
                a1[i] = sA1[kk][ty * TM + i];
                a2[i] = sA2[kk][ty * TM + i];
            }
#pragma unroll
            for (int j = 0; j < TN; j++) {
                w1[j] = sW1[kk][tx * TN + j];
                w2[j] = sW2[kk][tx * TN + j];
            }
#pragma unroll
            for (int i = 0; i < TM; i++)
#pragma unroll
                for (int j = 0; j < TN; j++) {
                    acc[i][j] += a1[i] * w1[j];
                    acc[i][j] += a2[i] * w2[j];
                }
        }
        __syncthreads();
    }

#pragma unroll
    for (int i = 0; i < TM; i++) {
        int m = m0 + ty * TM + i;
        if (m >= M) continue;
#pragma unroll
        for (int j = 0; j < TN; j++) {
            int n = n0 + tx * TN + j;
            if (n >= N) continue;
            float v = acc[i][j] + bias[n];
            C[(long)m * N + n] = fmaxf(v, 0.0f);
        }
    }
}

// ---------------- fp32 tiled GEMM, dual-B: one A pass, two outputs ----------------
// Layer 2: C1 = A@Wa (no bias), C2 = A@Wb + bias. M=NN, N=FOUT, K=HID.
__global__ __launch_bounds__(256)
void gemm2_k(const float* __restrict__ A,
             const float* __restrict__ Wa, const float* __restrict__ Wb,
             const float* __restrict__ bias,
             float* __restrict__ C1, float* __restrict__ C2,
             int M, int N, int K)
{
    constexpr int BM = 64, BN = 64, BK = 16, TM = 4, TN = 4;
    __shared__ float sA [BK][BM];
    __shared__ float sWa[BK][BN];
    __shared__ float sWb[BK][BN];

    const int tid = threadIdx.x;
    const int tx = tid % 16;
    const int ty = tid / 16;
    const int m0 = blockIdx.y * BM;
    const int n0 = blockIdx.x * BN;

    float acc1[TM][TN], acc2[TM][TN];
#pragma unroll
    for (int i = 0; i < TM; i++)
#pragma unroll
        for (int j = 0; j < TN; j++) { acc1[i][j] = 0.0f; acc2[i][j] = 0.0f; }

    const int arow = tid / 4;
    const int ac0  = (tid % 4) * 4;
    const int wcol = tid % 64;
    const int wr0  = tid / 64;

    for (int k0 = 0; k0 < K; k0 += BK) {
#pragma unroll
        for (int i = 0; i < 4; i++) {
            int k = k0 + ac0 + i;
            int m = m0 + arow;
            float v = 0.0f;
            if (m < M && k < K) v = A[(long)m * K + k];
            sA[ac0 + i][arow] = v;
        }
#pragma unroll
        for (int it = 0; it < 4; it++) {
            int kr = wr0 + it * 4;
            int k = k0 + kr;
            int n = n0 + wcol;
            float va = 0.0f, vb = 0.0f;
            if (k < K && n < N) {
                va = Wa[(long)k * N + n];
                vb = Wb[(long)k * N + n];
            }
            sWa[kr][wcol] = va;
            sWb[kr][wcol] = vb;
        }
        __syncthreads();

#pragma unroll
        for (int kk = 0; kk < BK; kk++) {
            float a[TM], wa[TN], wb[TN];
#pragma unroll
            for (int i = 0; i < TM; i++) a[i] = sA[kk][ty * TM + i];
#pragma unroll
            for (int j = 0; j < TN; j++) {
                wa[j] = sWa[kk][tx * TN + j];
                wb[j] = sWb[kk][tx * TN + j];
            }
#pragma unroll
            for (int i = 0; i < TM; i++)
#pragma unroll
                for (int j = 0; j < TN; j++) {
                    acc1[i][j] += a[i] * wa[j];
                    acc2[i][j] += a[i] * wb[j];
                }
        }
        __syncthreads();
    }

#pragma unroll
    for (int i = 0; i < TM; i++) {
        int m = m0 + ty * TM + i;
        if (m >= M) continue;
#pragma unroll
        for (int j = 0; j < TN; j++) {
            int n = n0 + tx * TN + j;
            if (n >= N) continue;
            C1[(long)m * N + n] = acc1[i][j];
            C2[(long)m * N + n] = acc2[i][j] + bias[n];
        }
    }
}

// ---------------- launch ----------------
extern "C" void kernel_launch(void* const* d_in, const int* in_sizes, int n_in,
                              void* d_out, int out_size)
{
    const float* x   = (const float*)d_in[0];
    const void*  ei  = d_in[1];
    const float* W1l = (const float*)d_in[2];
    const float* W1r = (const float*)d_in[3];
    const float* b1  = (const float*)d_in[4];
    const float* W2l = (const float*)d_in[5];
    const float* W2r = (const float*)d_in[6];
    const float* b2  = (const float*)d_in[7];
    float*       out = (float*)d_out;

    float *p_agg1, *p_h, *p_p;
    cudaGetSymbolAddress((void**)&p_agg1, g_agg1);
    cudaGetSymbolAddress((void**)&p_h,    g_h);
    cudaGetSymbolAddress((void**)&p_p,    g_p);

    // edge dtype detect + convert to int32
    k_detect<<<1, 256>>>((const int*)ei);
    k_convert<<<(2 * NE + 255) / 256, 256>>>(ei);

    // CSR by destination: histogram -> exclusive scan -> bucket fill
    k_zero2<<<(NN + 255) / 256, 256>>>();
    k_hist<<<(NE + 255) / 256, 256>>>();
    k_scan<<<1, 1024>>>();
    k_fill<<<(NE + 255) / 256, 256>>>();

    // layer 1: gather-mean of x (warp per dst), fused dual-A GEMM + bias + relu
    k_agg1<<<(NN * 32 + 255) / 256, 256>>>(x);
    {
        dim3 grid((HID + 63) / 64, (NN + 63) / 64);
        gemm1_k<<<grid, 256>>>(p_agg1, W1l, x, W1r, b1, p_h, NN, HID, FIN);
    }

    // layer 2: fused dual-B GEMM (p = h@W2_l, out = h@W2_r + b2),
    // then out += gather-mean of p (warp per dst; fuses old k_final)
    {
        dim3 grid((FOUT + 63) / 64, (NN + 63) / 64);
        gemm2_k<<<grid, 256>>>(p_h, W2l, W2r, b2, p_p, out, NN, FOUT, HID);
        k_agg2<<<(NN * 32 + 255) / 256, 256>>>(out);
    }
}